// round 1
// baseline (speedup 1.0000x reference)
#include <cuda_runtime.h>
#include <cuda_bf16.h>
#include <math.h>

#define NN    50000
#define EE    800000
#define ETOT  (EE + NN)     // edges + self loops
#define HH    4
#define CC    32
#define HC    128
#define NHID  512
#define NOUT  768
#define GG    256

// ---------------- scratch (device globals; no allocation allowed) ----------
__device__ float g_h [NN * HC];     // h = x @ W
__device__ float g_sk[NN * HC];     // skip = x @ skW
__device__ float g_x [NN * HC];     // layer output / next input
__device__ float g_esrc[NN * HH];
__device__ float g_edst[NN * HH];
__device__ int   g_deg[NN];
__device__ int   g_cnt[NN];
__device__ int   g_off[NN + 1];
__device__ int   g_srcidx[ETOT];
__device__ int   g_bsum[64];
__device__ int   g_bpre[64];
__device__ float g_pool[GG * HC];
__device__ float g_hid [GG * NHID];
__device__ int   g_is64;

// ---------------- dtype detection for edge_index / batch -------------------
__global__ void detect_k(const unsigned* __restrict__ w) {
    // If int64: every odd 32-bit word (high half of each nonneg id < 2^31) is 0.
    // If int32: odd words are node ids in [0,50000) -> essentially never all 0.
    int all0 = 1;
    for (int i = 0; i < 256; ++i)
        if (w[2 * i + 1] != 0u) { all0 = 0; break; }
    g_is64 = all0;
}

__device__ __forceinline__ int fetch_idx(const void* p, long i, int is64) {
    if (is64) return (int)((const long long*)p)[i];
    return ((const int*)p)[i];
}

// ---------------- init ------------------------------------------------------
__global__ void init_k() {
    int i = blockIdx.x * blockDim.x + threadIdx.x;
    if (i < NN) { g_deg[i] = 1; g_cnt[i] = 0; }          // deg starts at 1 (self loop)
    if (i < GG * HC) g_pool[i] = 0.0f;                    // matches ref empty-graph guard
}

__global__ void hist_k(const void* __restrict__ ei) {
    int e = blockIdx.x * blockDim.x + threadIdx.x;
    if (e >= EE) return;
    int is64 = g_is64;
    int d = fetch_idx(ei, (long)EE + e, is64);
    atomicAdd(&g_deg[d], 1);
}

// two-level inclusive scan over g_deg -> exclusive offsets in g_off
__global__ void scan1_k() {
    __shared__ int sh[1024];
    int t = threadIdx.x;
    int i = blockIdx.x * 1024 + t;
    int v = (i < NN) ? g_deg[i] : 0;
    sh[t] = v;
    for (int off = 1; off < 1024; off <<= 1) {
        __syncthreads();
        int x = (t >= off) ? sh[t - off] : 0;
        __syncthreads();
        sh[t] += x;
    }
    __syncthreads();
    if (i < NN) g_off[i] = sh[t];              // chunk-inclusive for now
    if (t == 1023) g_bsum[blockIdx.x] = sh[1023];
}

__global__ void scan2_k(int nblk) {
    if (threadIdx.x == 0) {
        int acc = 0;
        for (int b = 0; b < nblk; ++b) { g_bpre[b] = acc; acc += g_bsum[b]; }
    }
}

__global__ void scan3_k() {
    int t = threadIdx.x;
    int i = blockIdx.x * 1024 + t;
    if (i < NN) g_off[i] = g_off[i] + g_bpre[blockIdx.x] - g_deg[i];  // exclusive
    if (i == 0) g_off[NN] = ETOT;
}

__global__ void scatter_k(const void* __restrict__ ei) {
    long idx = (long)blockIdx.x * blockDim.x + threadIdx.x;
    if (idx >= ETOT) return;
    int is64 = g_is64;
    int s, d;
    if (idx < EE) {
        s = fetch_idx(ei, idx, is64);
        d = fetch_idx(ei, (long)EE + idx, is64);
    } else {
        s = d = (int)(idx - EE);
    }
    int p = g_off[d] + atomicAdd(&g_cnt[d], 1);
    g_srcidx[p] = s;
}

// ---------------- SGEMM: C[M,128] = A[M,128] @ B[128,128] ------------------
// 64x64 tile, 256 threads, 4x4 microtile, BK=16, float4 smem paths.
__global__ void gemm_k(const float* __restrict__ A, const float* __restrict__ B,
                       float* __restrict__ C, int M) {
    __shared__ float As[16][68];
    __shared__ float Bs[16][68];
    int tid = threadIdx.x;
    int m0 = blockIdx.x * 64, n0 = blockIdx.y * 64;
    int tm = (tid / 16) * 4, tn = (tid % 16) * 4;
    int ar = tid >> 2;             // 0..63
    int ak = (tid & 3) * 4;        // 0,4,8,12
    int bk = tid >> 4;             // 0..15
    int bc = (tid & 15) * 4;       // 0..60
    float c[4][4] = {};
    for (int k0 = 0; k0 < 128; k0 += 16) {
        float4 av = make_float4(0.f, 0.f, 0.f, 0.f);
        if (m0 + ar < M)
            av = *(const float4*)&A[(size_t)(m0 + ar) * 128 + k0 + ak];
        As[ak + 0][ar] = av.x; As[ak + 1][ar] = av.y;
        As[ak + 2][ar] = av.z; As[ak + 3][ar] = av.w;
        *(float4*)&Bs[bk][bc] = *(const float4*)&B[(size_t)(k0 + bk) * 128 + n0 + bc];
        __syncthreads();
#pragma unroll
        for (int kk = 0; kk < 16; ++kk) {
            float a[4], b[4];
            *(float4*)a = *(const float4*)&As[kk][tm];
            *(float4*)b = *(const float4*)&Bs[kk][tn];
#pragma unroll
            for (int i = 0; i < 4; ++i)
#pragma unroll
                for (int j = 0; j < 4; ++j)
                    c[i][j] += a[i] * b[j];
        }
        __syncthreads();
    }
#pragma unroll
    for (int i = 0; i < 4; ++i) {
        int row = m0 + tm + i;
        if (row < M)
            *(float4*)&C[(size_t)row * 128 + n0 + tn] =
                make_float4(c[i][0], c[i][1], c[i][2], c[i][3]);
    }
}

// ---------------- attention scores ------------------------------------------
__global__ void attn_k(const float* __restrict__ as_, const float* __restrict__ ad_) {
    int n = blockIdx.x * blockDim.x + threadIdx.x;
    if (n >= NN) return;
    const float* hr = &g_h[(size_t)n * 128];
#pragma unroll
    for (int h = 0; h < HH; ++h) {
        float s1 = 0.f, s2 = 0.f;
#pragma unroll
        for (int c = 0; c < CC; c += 4) {
            float4 hv = *(const float4*)&hr[h * CC + c];
            float4 a1 = *(const float4*)&as_[h * CC + c];
            float4 a2 = *(const float4*)&ad_[h * CC + c];
            s1 += hv.x * a1.x + hv.y * a1.y + hv.z * a1.z + hv.w * a1.w;
            s2 += hv.x * a2.x + hv.y * a2.y + hv.z * a2.z + hv.w * a2.w;
        }
        g_esrc[n * HH + h] = s1;
        g_edst[n * HH + h] = s2;
    }
}

// ---------------- warp-per-node online-softmax aggregation ------------------
__global__ void aggregate_k(const float* __restrict__ bias,
                            const float* __restrict__ skb) {
    int warp = (blockIdx.x * blockDim.x + threadIdx.x) >> 5;
    int lane = threadIdx.x & 31;
    if (warp >= NN) return;
    int n = warp;
    int head = lane >> 3;                      // features lane*4..lane*4+3 in head lane/8
    float ed = g_edst[n * HH + head];
    int j0 = g_off[n], j1 = g_off[n + 1];
    float m = -1e30f, z = 0.f;
    float4 acc = make_float4(0.f, 0.f, 0.f, 0.f);
    for (int j = j0; j < j1; ++j) {
        int s = g_srcidx[j];
        float e = g_esrc[s * HH + head] + ed;
        e = (e > 0.f) ? e : 0.2f * e;          // leaky relu 0.2
        float nm = fmaxf(m, e);
        float sc = __expf(m - nm);
        float w  = __expf(e - nm);
        float4 hv = *(const float4*)&g_h[(size_t)s * 128 + lane * 4];
        acc.x = acc.x * sc + w * hv.x;
        acc.y = acc.y * sc + w * hv.y;
        acc.z = acc.z * sc + w * hv.z;
        acc.w = acc.w * sc + w * hv.w;
        z = z * sc + w;
        m = nm;
    }
    float inv = 1.f / z;
    float4 sk = *(const float4*)&g_sk[(size_t)n * 128 + lane * 4];
    float4 bb = *(const float4*)&bias[lane * 4];
    float4 sb = *(const float4*)&skb[lane * 4];
    float4 o;
    o.x = fmaxf(0.f, acc.x * inv + bb.x + sk.x + sb.x);
    o.y = fmaxf(0.f, acc.y * inv + bb.y + sk.y + sb.y);
    o.z = fmaxf(0.f, acc.z * inv + bb.z + sk.z + sb.z);
    o.w = fmaxf(0.f, acc.w * inv + bb.w + sk.w + sb.w);
    *(float4*)&g_x[(size_t)n * 128 + lane * 4] = o;
}

// ---------------- global max pool --------------------------------------------
__global__ void pool_k(const void* __restrict__ batch) {
    int n = blockIdx.x;
    int t = threadIdx.x;     // 128 features
    int is64 = g_is64;
    int g = fetch_idx(batch, n, is64);
    float v = g_x[(size_t)n * 128 + t];
    // v >= 0 (post-ReLU) so int-compare atomicMax is monotone-correct
    atomicMax((int*)&g_pool[g * 128 + t], __float_as_int(v));
}

// ---------------- MLP --------------------------------------------------------
__global__ void mlp1_k(const float* __restrict__ w, const float* __restrict__ b) {
    __shared__ float sp[HC];
    int g = blockIdx.x, t = threadIdx.x;   // 512 threads
    if (t < HC) sp[t] = g_pool[g * HC + t];
    __syncthreads();
    float s = b[t];
#pragma unroll 8
    for (int k = 0; k < HC; ++k) s += sp[k] * w[(size_t)k * NHID + t];
    g_hid[(size_t)g * NHID + t] = fmaxf(s, 0.f);
}

__global__ void mlp2_k(const float* __restrict__ w, const float* __restrict__ b,
                       float* __restrict__ out) {
    __shared__ float sp[NHID];
    int g = blockIdx.x, t = threadIdx.x;   // 768 threads
    if (t < NHID) sp[t] = g_hid[(size_t)g * NHID + t];
    __syncthreads();
    float s = b[t];
#pragma unroll 8
    for (int k = 0; k < NHID; ++k) s += sp[k] * w[(size_t)k * NOUT + t];
    out[(size_t)g * NOUT + t] = s;
}

// ---------------- launch ------------------------------------------------------
extern "C" void kernel_launch(void* const* d_in, const int* in_sizes, int n_in,
                              void* d_out, int out_size) {
    const float* x     = (const float*)d_in[0];
    const void*  ei    = d_in[1];
    const void*  batch = d_in[2];
    const float* w[3]   = {(const float*)d_in[3],  (const float*)d_in[9],  (const float*)d_in[15]};
    const float* as_[3] = {(const float*)d_in[4],  (const float*)d_in[10], (const float*)d_in[16]};
    const float* ad_[3] = {(const float*)d_in[5],  (const float*)d_in[11], (const float*)d_in[17]};
    const float* b[3]   = {(const float*)d_in[6],  (const float*)d_in[12], (const float*)d_in[18]};
    const float* skw[3] = {(const float*)d_in[7],  (const float*)d_in[13], (const float*)d_in[19]};
    const float* skb[3] = {(const float*)d_in[8],  (const float*)d_in[14], (const float*)d_in[20]};
    const float* m1w = (const float*)d_in[21];
    const float* m1b = (const float*)d_in[22];
    const float* m2w = (const float*)d_in[23];
    const float* m2b = (const float*)d_in[24];
    float* out = (float*)d_out;

    float *ph, *psk, *px;
    cudaGetSymbolAddress((void**)&ph,  g_h);
    cudaGetSymbolAddress((void**)&psk, g_sk);
    cudaGetSymbolAddress((void**)&px,  g_x);

    const int SCAN_BLOCKS = (NN + 1023) / 1024;   // 49

    detect_k<<<1, 1>>>((const unsigned*)ei);
    init_k<<<(NN + 255) / 256, 256>>>();
    hist_k<<<(EE + 255) / 256, 256>>>(ei);
    scan1_k<<<SCAN_BLOCKS, 1024>>>();
    scan2_k<<<1, 32>>>(SCAN_BLOCKS);
    scan3_k<<<SCAN_BLOCKS, 1024>>>();
    scatter_k<<<(ETOT + 255) / 256, 256>>>(ei);

    dim3 ggrid((NN + 63) / 64, 2);
    for (int L = 0; L < 3; ++L) {
        const float* A = (L == 0) ? x : px;
        gemm_k<<<ggrid, 256>>>(A, w[L],   ph,  NN);
        gemm_k<<<ggrid, 256>>>(A, skw[L], psk, NN);
        attn_k<<<(NN + 127) / 128, 128>>>(as_[L], ad_[L]);
        aggregate_k<<<(NN * 32 + 255) / 256, 256>>>(b[L], skb[L]);
    }

    pool_k<<<NN, 128>>>(batch);
    mlp1_k<<<GG, NHID>>>(m1w, m1b);
    mlp2_k<<<GG, NOUT>>>(m2w, m2b, out);
}